// round 3
// baseline (speedup 1.0000x reference)
#include <cuda_runtime.h>
#include <cstdint>

#define HID   64
#define CHUNK 128
#define SEQS  4      // sequences per CTA
#define NTHR  128
#define NBLK  256    // 256 * 4 = 1024 sequences

typedef unsigned long long ull;

__device__ __forceinline__ ull pk2(float a, float b) {
    ull r; asm("mov.b64 %0, {%1, %2};" : "=l"(r) : "f"(a), "f"(b)); return r;
}
__device__ __forceinline__ void upk2(ull v, float &a, float &b) {
    asm("mov.b64 {%0, %1}, %2;" : "=f"(a), "=f"(b) : "l"(v));
}
__device__ __forceinline__ ull ffma2(ull a, ull b, ull c) {
    ull d; asm("fma.rn.f32x2 %0, %1, %2, %3;" : "=l"(d) : "l"(a), "l"(b), "l"(c)); return d;
}
__device__ __forceinline__ float fex2(float x){ float y; asm("ex2.approx.f32 %0, %1;" : "=f"(y) : "f"(x)); return y; }
__device__ __forceinline__ float frcp(float x){ float y; asm("rcp.approx.f32 %0, %1;" : "=f"(y) : "f"(x)); return y; }
// sigmoid(x) = 1 / (1 + 2^(-x*log2e))
__device__ __forceinline__ float fsig(float x){ return frcp(1.0f + fex2(-1.4426950408889634f * x)); }
// tanh(x) = 1 - 2 / (1 + 2^(2x*log2e))
__device__ __forceinline__ float ftanh_(float x){ return fmaf(-2.0f, frcp(1.0f + fex2(2.8853900817779268f * x)), 1.0f); }

__global__ void pc_zero_kernel(float* o) { if (threadIdx.x == 0) o[0] = 0.0f; }

__global__ void __launch_bounds__(NTHR, 2)
pc_lstm_kernel(const int*   __restrict__ inds,
               const float* __restrict__ p,
               const float* __restrict__ ls_probs,
               const float* __restrict__ open_probs,
               const int*   __restrict__ open_slices,
               const float* __restrict__ open_hx,
               const float* __restrict__ W_ih,
               const float* __restrict__ W_hh,
               const float* __restrict__ b_ih,
               const float* __restrict__ b_hh,
               const float* __restrict__ W_out,
               const float* __restrict__ b_out,
               const int*   __restrict__ n_chunks_ptr,
               float*       __restrict__ out)
{
    __shared__ __align__(16) ull   hsp[SEQS][HID];        // splatted (h,h) per seq element
    __shared__ __align__(16) ull   gsh[SEQS][HID];        // (tanh(g), sig(o)) from half 1
    __shared__ __align__(16) ull   xsh[SEQS][CHUNK][2];   // splatted (x0,x0),(x1,x1)
    __shared__ float  paysh[SEQS][CHUNK];
    __shared__ float  opwSh[SEQS];
    __shared__ float2 olpSh[SEQS];
    __shared__ int    baseSh[SEQS];

    const int tid  = threadIdx.x;
    const int j    = tid & 63;
    const int half = tid >> 6;      // 0: rows (j, j+64)=(i,f); 1: rows (j+128, j+192)=(g,o)
    const int w    = tid >> 5;      // warp index == sequence index for the output-dot phase
    const int lane = tid & 31;
    const int rowA = j + half * 128;
    const int rowB = rowA + 64;

    // ---- W_hh held entirely in registers: 64 x f32x2 packing (rowA, rowB) ----
    ull wreg[HID];
    #pragma unroll
    for (int k = 0; k < HID; ++k)
        wreg[k] = pk2(W_hh[rowA * HID + k], W_hh[rowB * HID + k]);

    const ull biasP = pk2(b_ih[rowA] + b_hh[rowA], b_ih[rowB] + b_hh[rowB]);
    const ull wih0  = pk2(W_ih[rowA * 2 + 0], W_ih[rowB * 2 + 0]);
    const ull wih1  = pk2(W_ih[rowA * 2 + 1], W_ih[rowB * 2 + 1]);

    const float wo0 = W_out[2 * lane];
    const float wo1 = W_out[2 * lane + 1];
    const float bo  = b_out[0];

    // per-sequence constants
    if (tid < SEQS) {
        int q = blockIdx.x * SEQS + tid;        // global sequence id
        baseSh[tid] = inds[q >> 4] + (q & 15);  // inds[a] + b  (B2 == 16)
        int sl = open_slices[q];
        olpSh[tid] = make_float2(logf(p[2 * sl]), logf(p[2 * sl + 1]));
        opwSh[tid] = open_probs[q] * (2.0f * ls_probs[q] - 1.0f);
    }

    // init h (shared, splatted) and c (half-0 registers)
    float cst[SEQS];
    #pragma unroll
    for (int s = 0; s < SEQS; ++s) cst[s] = 0.0f;
    if (half == 0) {
        #pragma unroll
        for (int s = 0; s < SEQS; ++s) {
            int q = blockIdx.x * SEQS + s;
            float h0 = open_hx[(q * 2 + 0) * HID + j];
            cst[s]   = open_hx[(q * 2 + 1) * HID + j];
            hsp[s][j] = pk2(h0, h0);
        }
    }
    __syncthreads();

    const int nch = n_chunks_ptr ? n_chunks_ptr[0] : 128;

    // serial prob-chain state per warp (== per sequence); redundant across lanes
    float  nd = 1.0f;
    double lossAcc = 0.0;

    for (int ch = 0; ch < nch; ++ch) {
        __syncthreads();  // protect xsh/paysh from previous chunk's readers
        // ---- chunk preamble: x inputs and payoff precompute ----
        for (int i = tid; i < SEQS * CHUNK; i += NTHR) {
            int s  = i >> 7;
            int tt = i & (CHUNK - 1);
            int b  = baseSh[s] + ch * CHUNK;
            float2 pv = ((const float2*)p)[b + tt];
            float2 pz = ((const float2*)p)[b];
            float x0 = pv.x - pz.x, x1 = pv.y - pz.y;
            xsh[s][tt][0] = pk2(x0, x0);
            xsh[s][tt][1] = pk2(x1, x1);
            paysh[s][tt] = opwSh[s] * ((logf(pv.x) - olpSh[s].x) + (logf(pv.y) - olpSh[s].y));
        }
        __syncthreads();

        for (int t = 0; t < CHUNK; ++t) {
            // ---- phase 1: g = bias + W_ih*x_t + W_hh*h (f32x2, W in registers) ----
            ull acc[SEQS];
            #pragma unroll
            for (int s = 0; s < SEQS; ++s) {
                ulonglong2 xv = *(const ulonglong2*)&xsh[s][t][0];
                acc[s] = ffma2(wih1, xv.y, ffma2(wih0, xv.x, biasP));
            }
            #pragma unroll
            for (int k2 = 0; k2 < HID / 2; ++k2) {
                #pragma unroll
                for (int s = 0; s < SEQS; ++s) {
                    ulonglong2 hh = *(const ulonglong2*)&hsp[s][2 * k2];
                    acc[s] = ffma2(wreg[2 * k2],     hh.x, acc[s]);
                    acc[s] = ffma2(wreg[2 * k2 + 1], hh.y, acc[s]);
                }
            }

            // ---- phase 2: gate nonlinearities ----
            float si[SEQS], sf[SEQS];
            if (half) {
                #pragma unroll
                for (int s = 0; s < SEQS; ++s) {
                    float gp, op_;
                    upk2(acc[s], gp, op_);
                    gsh[s][j] = pk2(ftanh_(gp), fsig(op_));
                }
            } else {
                #pragma unroll
                for (int s = 0; s < SEQS; ++s) {
                    float ip, fp;
                    upk2(acc[s], ip, fp);
                    si[s] = fsig(ip);
                    sf[s] = fsig(fp);
                }
            }
            __syncthreads();  // barrier A: gsh ready; all hsp reads of this step done

            // ---- phase 3: half 0 updates c, h; writes splatted h ----
            if (!half) {
                #pragma unroll
                for (int s = 0; s < SEQS; ++s) {
                    float tg, so;
                    upk2(gsh[s][j], tg, so);
                    cst[s] = sf[s] * cst[s] + si[s] * tg;
                    float h = so * ftanh_(cst[s]);
                    hsp[s][j] = pk2(h, h);
                }
            }
            __syncthreads();  // barrier B: new h visible to everyone

            // ---- phase 4: output dot + serial prob chain (warp w <-> seq w) ----
            {
                ulonglong2 hv = *(const ulonglong2*)&hsp[w][2 * lane];
                float h0, h1, dum;
                upk2(hv.x, h0, dum);
                upk2(hv.y, h1, dum);
                float part = fmaf(h0, wo0, h1 * wo1);
                #pragma unroll
                for (int o = 16; o; o >>= 1)
                    part += __shfl_xor_sync(0xffffffffu, part, o);
                float raw = fsig(part + bo);
                float pay = paysh[w][t];
                float adj = (t == 0) ? raw : raw * nd;
                if (lane == 0) lossAcc += (double)(adj * pay);
                if (t < CHUNK - 1) nd *= (1.0f - raw);
            }
        }
    }

    if (lane == 0) atomicAdd(out, (float)lossAcc);
}

extern "C" void kernel_launch(void* const* d_in, const int* in_sizes, int n_in,
                              void* d_out, int out_size)
{
    const int*   inds        = (const int*)  d_in[0];
    const float* p           = (const float*)d_in[1];
    const float* ls_probs    = (const float*)d_in[2];
    const float* open_probs  = (const float*)d_in[3];
    const int*   open_slices = (const int*)  d_in[4];
    const float* open_hx     = (const float*)d_in[5];
    const float* W_ih        = (const float*)d_in[6];
    const float* W_hh        = (const float*)d_in[7];
    const float* b_ih        = (const float*)d_in[8];
    const float* b_hh        = (const float*)d_in[9];
    const float* W_out       = (const float*)d_in[10];
    const float* b_out       = (const float*)d_in[11];
    const int*   n_chunks    = (n_in > 12) ? (const int*)d_in[12] : nullptr;

    float* out = (float*)d_out;

    pc_zero_kernel<<<1, 32>>>(out);
    pc_lstm_kernel<<<NBLK, NTHR>>>(inds, p, ls_probs, open_probs, open_slices,
                                   open_hx, W_ih, W_hh, b_ih, b_hh,
                                   W_out, b_out, n_chunks, out);
}

// round 4
// speedup vs baseline: 1.0136x; 1.0136x over previous
#include <cuda_runtime.h>
#include <cstdint>

#define HID   64
#define CHUNK 128
#define SEQS  4      // sequences per CTA
#define NTHR  128
#define NBLK  256    // 256 * 4 = 1024 sequences

typedef unsigned long long ull;

__device__ __forceinline__ ull pk2(float a, float b) {
    ull r; asm("mov.b64 %0, {%1, %2};" : "=l"(r) : "f"(a), "f"(b)); return r;
}
__device__ __forceinline__ void upk2(ull v, float &a, float &b) {
    asm("mov.b64 {%0, %1}, %2;" : "=f"(a), "=f"(b) : "l"(v));
}
__device__ __forceinline__ ull ffma2(ull a, ull b, ull c) {
    ull d; asm("fma.rn.f32x2 %0, %1, %2, %3;" : "=l"(d) : "l"(a), "l"(b), "l"(c)); return d;
}
__device__ __forceinline__ float fex2(float x){ float y; asm("ex2.approx.f32 %0, %1;" : "=f"(y) : "f"(x)); return y; }
__device__ __forceinline__ float frcp(float x){ float y; asm("rcp.approx.f32 %0, %1;" : "=f"(y) : "f"(x)); return y; }
// sigmoid(x) = 1 / (1 + 2^(-x*log2e))
__device__ __forceinline__ float fsig(float x){ return frcp(1.0f + fex2(-1.4426950408889634f * x)); }
// tanh(x) = 1 - 2 / (1 + 2^(2x*log2e))
__device__ __forceinline__ float ftanh_(float x){ return fmaf(-2.0f, frcp(1.0f + fex2(2.8853900817779268f * x)), 1.0f); }

__global__ void pc_zero_kernel(float* o) { if (threadIdx.x == 0) o[0] = 0.0f; }

__global__ void __launch_bounds__(NTHR, 2)
pc_lstm_kernel(const int*   __restrict__ inds,
               const float* __restrict__ p,
               const float* __restrict__ ls_probs,
               const float* __restrict__ open_probs,
               const int*   __restrict__ open_slices,
               const float* __restrict__ open_hx,
               const float* __restrict__ W_ih,
               const float* __restrict__ W_hh,
               const float* __restrict__ b_ih,
               const float* __restrict__ b_hh,
               const float* __restrict__ W_out,
               const float* __restrict__ b_out,
               const int*   __restrict__ n_chunks_ptr,
               float*       __restrict__ out)
{
    // double-buffered splatted h: (h,h) pairs for f32x2
    __shared__ __align__(16) ull   hsp[2][SEQS][HID];
    __shared__ __align__(16) ull   xsh[SEQS][CHUNK][2];   // splatted (x0,x0),(x1,x1)
    __shared__ float  paysh[SEQS][CHUNK];
    __shared__ float  opwSh[SEQS];
    __shared__ float2 olpSh[SEQS];
    __shared__ int    baseSh[SEQS];

    const int tid  = threadIdx.x;
    const int e    = tid >> 1;      // element 0..63
    const int od   = tid & 1;       // 0: rows (i_e, g_e); 1: rows (f_e, o_e)
    const int w    = tid >> 5;      // warp index == sequence index for phase 4
    const int lane = tid & 31;
    const int rowA = e + od * 64;          // i_e or f_e
    const int rowB = e + 128 + od * 64;    // g_e or o_e

    // ---- W_hh register-resident: 64 x f32x2 packing (rowA, rowB) = 128 regs ----
    ull wreg[HID];
    #pragma unroll
    for (int k = 0; k < HID; ++k)
        wreg[k] = pk2(W_hh[rowA * HID + k], W_hh[rowB * HID + k]);

    const ull biasP = pk2(b_ih[rowA] + b_hh[rowA], b_ih[rowB] + b_hh[rowB]);
    const ull wih0  = pk2(W_ih[rowA * 2 + 0], W_ih[rowB * 2 + 0]);
    const ull wih1  = pk2(W_ih[rowA * 2 + 1], W_ih[rowB * 2 + 1]);

    const float wo0 = W_out[2 * lane];
    const float wo1 = W_out[2 * lane + 1];
    const float bo  = b_out[0];

    if (tid < SEQS) {
        int q = blockIdx.x * SEQS + tid;        // global sequence id
        baseSh[tid] = inds[q >> 4] + (q & 15);  // inds[a] + b  (B2 == 16)
        int sl = open_slices[q];
        olpSh[tid] = make_float2(logf(p[2 * sl]), logf(p[2 * sl + 1]));
        opwSh[tid] = open_probs[q] * (2.0f * ls_probs[q] - 1.0f);
    }

    // init c (both lanes, redundant) and h (even lane publishes)
    float cst[SEQS];
    #pragma unroll
    for (int s = 0; s < SEQS; ++s) {
        int q = blockIdx.x * SEQS + s;
        cst[s] = open_hx[(q * 2 + 1) * HID + e];
        if (!od) {
            float h0 = open_hx[(q * 2 + 0) * HID + e];
            hsp[0][s][e] = pk2(h0, h0);
        }
    }
    __syncthreads();

    const int nch = n_chunks_ptr ? n_chunks_ptr[0] : 128;

    float  nd = 1.0f;           // survival prob chain (per warp == per seq, redundant per lane)
    double lossAcc = 0.0;
    int    cur = 0;             // 128 steps/chunk (even) -> cur is 0 at every chunk start

    for (int ch = 0; ch < nch; ++ch) {
        __syncthreads();  // xsh/paysh of previous chunk fully consumed
        // ---- chunk preamble: inputs + payoff precompute ----
        for (int i = tid; i < SEQS * CHUNK; i += NTHR) {
            int s  = i >> 7;
            int tt = i & (CHUNK - 1);
            int b  = baseSh[s] + ch * CHUNK;
            float2 pv = ((const float2*)p)[b + tt];
            float2 pz = ((const float2*)p)[b];
            float x0 = pv.x - pz.x, x1 = pv.y - pz.y;
            xsh[s][tt][0] = pk2(x0, x0);
            xsh[s][tt][1] = pk2(x1, x1);
            paysh[s][tt] = opwSh[s] * ((logf(pv.x) - olpSh[s].x) + (logf(pv.y) - olpSh[s].y));
        }
        __syncthreads();

        #pragma unroll 1
        for (int t = 0; t < CHUNK; ++t) {
            // ---- phase 1: g_pre = bias + W_ih*x_t + W_hh*h  (f32x2, W in regs) ----
            ull acc[SEQS];
            #pragma unroll
            for (int s = 0; s < SEQS; ++s) {
                ulonglong2 xv = *(const ulonglong2*)&xsh[s][t][0];
                acc[s] = ffma2(wih1, xv.y, ffma2(wih0, xv.x, biasP));
            }
            #pragma unroll
            for (int k2 = 0; k2 < HID / 2; ++k2) {
                #pragma unroll
                for (int s = 0; s < SEQS; ++s) {
                    ulonglong2 hh = *(const ulonglong2*)&hsp[cur][s][2 * k2];
                    acc[s] = ffma2(wreg[2 * k2],     hh.x, acc[s]);
                    acc[s] = ffma2(wreg[2 * k2 + 1], hh.y, acc[s]);
                }
            }

            // ---- lagged phase 4 (step t-1): overlaps with FMA stream above ----
            if (t) {
                ulonglong2 hv = *(const ulonglong2*)&hsp[cur][w][2 * lane];
                float h0, h1, dum;
                upk2(hv.x, h0, dum);
                upk2(hv.y, h1, dum);
                float part = fmaf(h0, wo0, h1 * wo1);
                #pragma unroll
                for (int o = 16; o; o >>= 1)
                    part += __shfl_xor_sync(0xffffffffu, part, o);
                float raw = fsig(part + bo);
                float pay = paysh[w][t - 1];
                float adj = (t - 1 == 0) ? raw : raw * nd;
                lossAcc += (double)(adj * pay);
                nd *= (1.0f - raw);          // t-1 <= 126 here: always update
            }

            // ---- phase 2+3: intra-pair gate exchange, redundant c/h update ----
            #pragma unroll
            for (int s = 0; s < SEQS; ++s) {
                float a0, a1;
                upk2(acc[s], a0, a1);
                float b0 = __shfl_xor_sync(0xffffffffu, a0, 1);
                float b1 = __shfl_xor_sync(0xffffffffu, a1, 1);
                float ipre = od ? b0 : a0;   // SELs, no divergence
                float gpre = od ? b1 : a1;
                float fpre = od ? a0 : b0;
                float opre = od ? a1 : b1;
                float si = fsig(ipre), sf = fsig(fpre);
                float tg = ftanh_(gpre), so = fsig(opre);
                cst[s] = sf * cst[s] + si * tg;
                float h = so * ftanh_(cst[s]);
                if (!od) hsp[cur ^ 1][s][e] = pk2(h, h);
            }
            __syncthreads();   // single barrier per step: h published, buffers rotated
            cur ^= 1;
        }

        // ---- trailing phase 4 for t = CHUNK-1 (before preamble overwrites paysh) ----
        {
            ulonglong2 hv = *(const ulonglong2*)&hsp[cur][w][2 * lane];
            float h0, h1, dum;
            upk2(hv.x, h0, dum);
            upk2(hv.y, h1, dum);
            float part = fmaf(h0, wo0, h1 * wo1);
            #pragma unroll
            for (int o = 16; o; o >>= 1)
                part += __shfl_xor_sync(0xffffffffu, part, o);
            float raw = fsig(part + bo);
            float pay = paysh[w][CHUNK - 1];
            lossAcc += (double)(raw * nd * pay);
            // last element of chunk: nd NOT updated (matches cumprod over [:-1])
        }
    }

    if (lane == 0) atomicAdd(out, (float)lossAcc);
}

extern "C" void kernel_launch(void* const* d_in, const int* in_sizes, int n_in,
                              void* d_out, int out_size)
{
    const int*   inds        = (const int*)  d_in[0];
    const float* p           = (const float*)d_in[1];
    const float* ls_probs    = (const float*)d_in[2];
    const float* open_probs  = (const float*)d_in[3];
    const int*   open_slices = (const int*)  d_in[4];
    const float* open_hx     = (const float*)d_in[5];
    const float* W_ih        = (const float*)d_in[6];
    const float* W_hh        = (const float*)d_in[7];
    const float* b_ih        = (const float*)d_in[8];
    const float* b_hh        = (const float*)d_in[9];
    const float* W_out       = (const float*)d_in[10];
    const float* b_out       = (const float*)d_in[11];
    const int*   n_chunks    = (n_in > 12) ? (const int*)d_in[12] : nullptr;

    float* out = (float*)d_out;

    pc_zero_kernel<<<1, 32>>>(out);
    pc_lstm_kernel<<<NBLK, NTHR>>>(inds, p, ls_probs, open_probs, open_slices,
                                   open_hx, W_ih, W_hh, b_ih, b_hh,
                                   W_out, b_out, n_chunks, out);
}

// round 5
// speedup vs baseline: 1.1720x; 1.1563x over previous
#include <cuda_runtime.h>
#include <cstdint>

#define HID   64
#define CHUNK 128
#define SEQS  4      // sequences per CTA
#define NTHR  128
#define NBLK  256    // 256 * 4 = 1024 sequences

typedef unsigned long long ull;

__device__ __forceinline__ ull pk2(float a, float b) {
    ull r; asm("mov.b64 %0, {%1, %2};" : "=l"(r) : "f"(a), "f"(b)); return r;
}
__device__ __forceinline__ void upk2(ull v, float &a, float &b) {
    asm("mov.b64 {%0, %1}, %2;" : "=f"(a), "=f"(b) : "l"(v));
}
__device__ __forceinline__ ull ffma2(ull a, ull b, ull c) {
    ull d; asm("fma.rn.f32x2 %0, %1, %2, %3;" : "=l"(d) : "l"(a), "l"(b), "l"(c)); return d;
}
// single-MUFU tanh (sm_75+): MUFU.TANH
__device__ __forceinline__ float ftanh_(float x){
    float y; asm("tanh.approx.f32 %0, %1;" : "=f"(y) : "f"(x)); return y;
}
// sigmoid(x) = 0.5*tanh(0.5x) + 0.5  -> 1 MUL + 1 MUFU + 1 FMA
__device__ __forceinline__ float fsig(float x){
    return fmaf(0.5f, ftanh_(0.5f * x), 0.5f);
}

__global__ void pc_zero_kernel(float* o) { if (threadIdx.x == 0) o[0] = 0.0f; }

__global__ void __launch_bounds__(NTHR, 2)
pc_lstm_kernel(const int*   __restrict__ inds,
               const float* __restrict__ p,
               const float* __restrict__ ls_probs,
               const float* __restrict__ open_probs,
               const int*   __restrict__ open_slices,
               const float* __restrict__ open_hx,
               const float* __restrict__ W_ih,
               const float* __restrict__ W_hh,
               const float* __restrict__ b_ih,
               const float* __restrict__ b_hh,
               const float* __restrict__ W_out,
               const float* __restrict__ b_out,
               const int*   __restrict__ n_chunks_ptr,
               float*       __restrict__ out)
{
    // double-buffered splatted h: (h,h) pairs for f32x2
    __shared__ __align__(16) ull   hsp[2][SEQS][HID];
    __shared__ __align__(16) ull   xsh[SEQS][CHUNK][2];   // splatted (x0,x0),(x1,x1)
    __shared__ float  paysh[SEQS][CHUNK];
    __shared__ float  opwSh[SEQS];
    __shared__ float2 olpSh[SEQS];
    __shared__ int    baseSh[SEQS];

    const int tid  = threadIdx.x;
    const int e    = tid >> 1;      // element 0..63
    const int od   = tid & 1;       // 0: rows (i_e, g_e); 1: rows (f_e, o_e)
    const int w    = tid >> 5;      // warp index == sequence index for phase 4
    const int lane = tid & 31;
    const int rowA = e + od * 64;          // i_e or f_e
    const int rowB = e + 128 + od * 64;    // g_e or o_e

    // ---- W_hh register-resident: 64 x f32x2 packing (rowA, rowB) = 128 regs ----
    ull wreg[HID];
    #pragma unroll
    for (int k = 0; k < HID; ++k)
        wreg[k] = pk2(W_hh[rowA * HID + k], W_hh[rowB * HID + k]);

    const ull biasP = pk2(b_ih[rowA] + b_hh[rowA], b_ih[rowB] + b_hh[rowB]);
    const ull wih0  = pk2(W_ih[rowA * 2 + 0], W_ih[rowB * 2 + 0]);
    const ull wih1  = pk2(W_ih[rowA * 2 + 1], W_ih[rowB * 2 + 1]);

    const float wo0 = W_out[2 * lane];
    const float wo1 = W_out[2 * lane + 1];
    const float bo  = b_out[0];

    if (tid < SEQS) {
        int q = blockIdx.x * SEQS + tid;        // global sequence id
        baseSh[tid] = inds[q >> 4] + (q & 15);  // inds[a] + b  (B2 == 16)
        int sl = open_slices[q];
        olpSh[tid] = make_float2(__logf(p[2 * sl]), __logf(p[2 * sl + 1]));
        opwSh[tid] = open_probs[q] * (2.0f * ls_probs[q] - 1.0f);
    }

    // init c (both lanes, redundant) and h (even lane publishes)
    float cst[SEQS];
    #pragma unroll
    for (int s = 0; s < SEQS; ++s) {
        int q = blockIdx.x * SEQS + s;
        cst[s] = open_hx[(q * 2 + 1) * HID + e];
        if (!od) {
            float h0 = open_hx[(q * 2 + 0) * HID + e];
            hsp[0][s][e] = pk2(h0, h0);
        }
    }
    __syncthreads();

    const int nch = n_chunks_ptr ? n_chunks_ptr[0] : 128;

    float  nd = 1.0f;           // survival prob chain (per warp == per seq, redundant per lane)
    double lossAcc = 0.0;
    int    cur = 0;             // 128 steps/chunk (even) -> cur == 0 at every chunk start

    for (int ch = 0; ch < nch; ++ch) {
        __syncthreads();  // xsh/paysh of previous chunk fully consumed
        // ---- chunk preamble: inputs + payoff precompute ----
        for (int i = tid; i < SEQS * CHUNK; i += NTHR) {
            int s  = i >> 7;
            int tt = i & (CHUNK - 1);
            int b  = baseSh[s] + ch * CHUNK;
            float2 pv = ((const float2*)p)[b + tt];
            float2 pz = ((const float2*)p)[b];
            float x0 = pv.x - pz.x, x1 = pv.y - pz.y;
            xsh[s][tt][0] = pk2(x0, x0);
            xsh[s][tt][1] = pk2(x1, x1);
            paysh[s][tt] = opwSh[s] * ((__logf(pv.x) - olpSh[s].x) + (__logf(pv.y) - olpSh[s].y));
        }
        __syncthreads();

        // prefetch step-0 input term: accI = bias + W_ih * x_0
        ull accI[SEQS];
        #pragma unroll
        for (int s = 0; s < SEQS; ++s) {
            ulonglong2 xv = *(const ulonglong2*)&xsh[s][0][0];
            accI[s] = ffma2(wih1, xv.y, ffma2(wih0, xv.x, biasP));
        }

        #pragma unroll 1
        for (int t = 0; t < CHUNK; ++t) {
            // ---- lagged phase 4 hsp read: issue the LDS early ----
            ulonglong2 hv;
            if (t) hv = *(const ulonglong2*)&hsp[cur][w][2 * lane];

            // ---- phase 1: acc = accI(prefetched) + W_hh * h  (f32x2, W in regs) ----
            ull acc[SEQS];
            #pragma unroll
            for (int s = 0; s < SEQS; ++s) acc[s] = accI[s];
            #pragma unroll
            for (int k2 = 0; k2 < HID / 2; ++k2) {
                #pragma unroll
                for (int s = 0; s < SEQS; ++s) {
                    ulonglong2 hh = *(const ulonglong2*)&hsp[cur][s][2 * k2];
                    acc[s] = ffma2(wreg[2 * k2],     hh.x, acc[s]);
                    acc[s] = ffma2(wreg[2 * k2 + 1], hh.y, acc[s]);
                }
            }

            // ---- lagged phase 4 (step t-1): overlaps with the FMA stream above ----
            if (t) {
                float h0, h1, dum;
                upk2(hv.x, h0, dum);
                upk2(hv.y, h1, dum);
                float part = fmaf(h0, wo0, h1 * wo1);
                #pragma unroll
                for (int o = 16; o; o >>= 1)
                    part += __shfl_xor_sync(0xffffffffu, part, o);
                float raw = fsig(part + bo);
                float pay = paysh[w][t - 1];
                float adj = (t - 1 == 0) ? raw : raw * nd;
                lossAcc += (double)(adj * pay);
                nd *= (1.0f - raw);          // t-1 <= 126 here: always update
            }

            // ---- prefetch next step's input term (chunk-static xsh; no hazard) ----
            {
                int tn = (t + 1 < CHUNK) ? t + 1 : t;
                #pragma unroll
                for (int s = 0; s < SEQS; ++s) {
                    ulonglong2 xv = *(const ulonglong2*)&xsh[s][tn][0];
                    accI[s] = ffma2(wih1, xv.y, ffma2(wih0, xv.x, biasP));
                }
            }

            // ---- phase 2+3: intra-pair gate exchange, redundant c/h update ----
            #pragma unroll
            for (int s = 0; s < SEQS; ++s) {
                float a0, a1;
                upk2(acc[s], a0, a1);
                float b0 = __shfl_xor_sync(0xffffffffu, a0, 1);
                float b1 = __shfl_xor_sync(0xffffffffu, a1, 1);
                float ipre = od ? b0 : a0;   // SELs, no divergence
                float gpre = od ? b1 : a1;
                float fpre = od ? a0 : b0;
                float opre = od ? a1 : b1;
                float si = fsig(ipre), sf = fsig(fpre);
                float tg = ftanh_(gpre), so = fsig(opre);
                cst[s] = sf * cst[s] + si * tg;
                float h = so * ftanh_(cst[s]);
                if (!od) hsp[cur ^ 1][s][e] = pk2(h, h);
            }
            __syncthreads();   // single barrier per step: h published, buffers rotated
            cur ^= 1;
        }

        // ---- trailing phase 4 for t = CHUNK-1 (before preamble overwrites paysh) ----
        {
            ulonglong2 hv = *(const ulonglong2*)&hsp[cur][w][2 * lane];
            float h0, h1, dum;
            upk2(hv.x, h0, dum);
            upk2(hv.y, h1, dum);
            float part = fmaf(h0, wo0, h1 * wo1);
            #pragma unroll
            for (int o = 16; o; o >>= 1)
                part += __shfl_xor_sync(0xffffffffu, part, o);
            float raw = fsig(part + bo);
            float pay = paysh[w][CHUNK - 1];
            lossAcc += (double)(raw * nd * pay);
            // last element of chunk: nd NOT updated (matches cumprod over [:-1])
        }
    }

    if (lane == 0) atomicAdd(out, (float)lossAcc);
}

extern "C" void kernel_launch(void* const* d_in, const int* in_sizes, int n_in,
                              void* d_out, int out_size)
{
    const int*   inds        = (const int*)  d_in[0];
    const float* p           = (const float*)d_in[1];
    const float* ls_probs    = (const float*)d_in[2];
    const float* open_probs  = (const float*)d_in[3];
    const int*   open_slices = (const int*)  d_in[4];
    const float* open_hx     = (const float*)d_in[5];
    const float* W_ih        = (const float*)d_in[6];
    const float* W_hh        = (const float*)d_in[7];
    const float* b_ih        = (const float*)d_in[8];
    const float* b_hh        = (const float*)d_in[9];
    const float* W_out       = (const float*)d_in[10];
    const float* b_out       = (const float*)d_in[11];
    const int*   n_chunks    = (n_in > 12) ? (const int*)d_in[12] : nullptr;

    float* out = (float*)d_out;

    pc_zero_kernel<<<1, 32>>>(out);
    pc_lstm_kernel<<<NBLK, NTHR>>>(inds, p, ls_probs, open_probs, open_slices,
                                   open_hx, W_ih, W_hh, b_ih, b_hh,
                                   W_out, b_out, n_chunks, out);
}

// round 7
// speedup vs baseline: 1.4734x; 1.2571x over previous
#include <cuda_runtime.h>
#include <cstdint>

#define HID   64
#define CHUNK 128
#define SEQS  4      // sequences per CTA
#define NTHR  128
#define NBLK  256    // 256 * 4 = 1024 sequences

typedef unsigned long long ull;

__device__ __forceinline__ ull pk2(float a, float b) {
    ull r; asm("mov.b64 %0, {%1, %2};" : "=l"(r) : "f"(a), "f"(b)); return r;
}
__device__ __forceinline__ void upk2(ull v, float &a, float &b) {
    asm("mov.b64 {%0, %1}, %2;" : "=f"(a), "=f"(b) : "l"(v));
}
__device__ __forceinline__ ull ffma2(ull a, ull b, ull c) {
    ull d; asm("fma.rn.f32x2 %0, %1, %2, %3;" : "=l"(d) : "l"(a), "l"(b), "l"(c)); return d;
}
// single-MUFU tanh (sm_75+): MUFU.TANH
__device__ __forceinline__ float ftanh_(float x){
    float y; asm("tanh.approx.f32 %0, %1;" : "=f"(y) : "f"(x)); return y;
}
// sigmoid(x) = 0.5*tanh(0.5x) + 0.5  -> 1 MUL + 1 MUFU + 1 FMA
__device__ __forceinline__ float fsig(float x){
    return fmaf(0.5f, ftanh_(0.5f * x), 0.5f);
}

__global__ void pc_zero_kernel(float* o) { if (threadIdx.x == 0) o[0] = 0.0f; }

__global__ void __launch_bounds__(NTHR, 2)
pc_lstm_kernel(const int*   __restrict__ inds,
               const float* __restrict__ p,
               const float* __restrict__ ls_probs,
               const float* __restrict__ open_probs,
               const int*   __restrict__ open_slices,
               const float* __restrict__ open_hx,
               const float* __restrict__ W_ih,
               const float* __restrict__ W_hh,
               const float* __restrict__ b_ih,
               const float* __restrict__ b_hh,
               const float* __restrict__ W_out,
               const float* __restrict__ b_out,
               const int*   __restrict__ n_chunks_ptr,
               float*       __restrict__ out)
{
    // double-buffered h, stored UNSPLATTED: 64 plain floats per seq
    __shared__ __align__(16) float hspF[2][SEQS][HID];
    __shared__ __align__(16) ull   xsh[SEQS][CHUNK][2];   // splatted (x0,x0),(x1,x1)
    __shared__ float  paysh[SEQS][CHUNK];
    __shared__ float  opwSh[SEQS];
    __shared__ float2 olpSh[SEQS];
    __shared__ int    baseSh[SEQS];

    const int tid  = threadIdx.x;
    const int e    = tid >> 1;      // element 0..63
    const int od   = tid & 1;       // 0: rows (i_e, g_e); 1: rows (f_e, o_e)
    const int w    = tid >> 5;      // warp index == sequence index for phase 4
    const int lane = tid & 31;
    const int rowA = e + od * 64;          // i_e or f_e
    const int rowB = e + 128 + od * 64;    // g_e or o_e

    // ---- W_hh register-resident, k-pair packed: 2 rows x 32 f32x2 = 128 regs ----
    ull wregA[HID / 2], wregB[HID / 2];
    #pragma unroll
    for (int k2 = 0; k2 < HID / 2; ++k2) {
        wregA[k2] = pk2(W_hh[rowA * HID + 2 * k2], W_hh[rowA * HID + 2 * k2 + 1]);
        wregB[k2] = pk2(W_hh[rowB * HID + 2 * k2], W_hh[rowB * HID + 2 * k2 + 1]);
    }

    const ull biasP = pk2(b_ih[rowA] + b_hh[rowA], b_ih[rowB] + b_hh[rowB]);
    const ull wih0  = pk2(W_ih[rowA * 2 + 0], W_ih[rowB * 2 + 0]);
    const ull wih1  = pk2(W_ih[rowA * 2 + 1], W_ih[rowB * 2 + 1]);

    const float wo0 = W_out[2 * lane];
    const float wo1 = W_out[2 * lane + 1];
    const float bo  = b_out[0];

    if (tid < SEQS) {
        int q = blockIdx.x * SEQS + tid;        // global sequence id
        baseSh[tid] = inds[q >> 4] + (q & 15);  // inds[a] + b  (B2 == 16)
        int sl = open_slices[q];
        olpSh[tid] = make_float2(__logf(p[2 * sl]), __logf(p[2 * sl + 1]));
        opwSh[tid] = open_probs[q] * (2.0f * ls_probs[q] - 1.0f);
    }

    // init c (both lanes, redundant) and h (even lane publishes, plain float)
    float cst[SEQS];
    #pragma unroll
    for (int s = 0; s < SEQS; ++s) {
        int q = blockIdx.x * SEQS + s;
        cst[s] = open_hx[(q * 2 + 1) * HID + e];
        if (!od) hspF[0][s][e] = open_hx[(q * 2 + 0) * HID + e];
    }
    __syncthreads();

    const int nch = n_chunks_ptr ? n_chunks_ptr[0] : 128;

    float  nd = 1.0f;           // survival prob chain (per warp == per seq, redundant per lane)
    double lossAcc = 0.0;
    int    cur = 0;             // 128 steps/chunk (even) -> cur == 0 at every chunk start

    for (int ch = 0; ch < nch; ++ch) {
        __syncthreads();  // xsh/paysh of previous chunk fully consumed
        // ---- chunk preamble: inputs + payoff precompute ----
        for (int i = tid; i < SEQS * CHUNK; i += NTHR) {
            int s  = i >> 7;
            int tt = i & (CHUNK - 1);
            int b  = baseSh[s] + ch * CHUNK;
            float2 pv = ((const float2*)p)[b + tt];
            float2 pz = ((const float2*)p)[b];
            float x0 = pv.x - pz.x, x1 = pv.y - pz.y;
            xsh[s][tt][0] = pk2(x0, x0);
            xsh[s][tt][1] = pk2(x1, x1);
            paysh[s][tt] = opwSh[s] * ((__logf(pv.x) - olpSh[s].x) + (__logf(pv.y) - olpSh[s].y));
        }
        __syncthreads();

        // prefetch step-0 input term: accI = bias + W_ih * x_0   (lanes = rowA,rowB)
        ull accI[SEQS];
        #pragma unroll
        for (int s = 0; s < SEQS; ++s) {
            ulonglong2 xv = *(const ulonglong2*)&xsh[s][0][0];
            accI[s] = ffma2(wih1, xv.y, ffma2(wih0, xv.x, biasP));
        }

        #pragma unroll 1
        for (int t = 0; t < CHUNK; ++t) {
            // ---- lagged phase 4 h read: issue the LDS early (plain float2) ----
            float2 hv;
            if (t) hv = *(const float2*)&hspF[cur][w][2 * lane];

            // ---- phase 1: k-packed matvec, h unsplatted, W in regs ----
            ull accA[SEQS], accB[SEQS];
            #pragma unroll
            for (int s = 0; s < SEQS; ++s) { accA[s] = 0ull; accB[s] = 0ull; }
            #pragma unroll
            for (int k4 = 0; k4 < HID / 4; ++k4) {        // 16 iters: 16B LDS -> 4 h values
                #pragma unroll
                for (int s = 0; s < SEQS; ++s) {
                    ulonglong2 hh = *(const ulonglong2*)&hspF[cur][s][4 * k4];
                    accA[s] = ffma2(wregA[2 * k4],     hh.x, accA[s]);
                    accB[s] = ffma2(wregB[2 * k4],     hh.x, accB[s]);
                    accA[s] = ffma2(wregA[2 * k4 + 1], hh.y, accA[s]);
                    accB[s] = ffma2(wregB[2 * k4 + 1], hh.y, accB[s]);
                }
            }

            // ---- lagged phase 4 (step t-1): overlaps with the FMA stream above ----
            if (t) {
                float part = fmaf(hv.x, wo0, hv.y * wo1);
                #pragma unroll
                for (int o = 16; o; o >>= 1)
                    part += __shfl_xor_sync(0xffffffffu, part, o);
                float raw = fsig(part + bo);
                float pay = paysh[w][t - 1];
                float adj = (t - 1 == 0) ? raw : raw * nd;
                lossAcc += (double)(adj * pay);
                nd *= (1.0f - raw);          // t-1 <= 126 here: always update
            }

            // ---- prefetch NEXT step's input term into accN (consumed next iter) ----
            ull accN[SEQS];
            {
                int tn = (t + 1 < CHUNK) ? t + 1 : t;
                #pragma unroll
                for (int s = 0; s < SEQS; ++s) {
                    ulonglong2 xv = *(const ulonglong2*)&xsh[s][tn][0];
                    accN[s] = ffma2(wih1, xv.y, ffma2(wih0, xv.x, biasP));
                }
            }

            // ---- phase 2+3: fold (uses CURRENT accI), gate exchange, c/h update ----
            #pragma unroll
            for (int s = 0; s < SEQS; ++s) {
                float inA, inB, lA, hA, lB, hB;
                upk2(accI[s], inA, inB);
                upk2(accA[s], lA, hA);
                upk2(accB[s], lB, hB);
                float a0 = (lA + hA) + inA;    // pre-activation of rowA (i or f)
                float a1 = (lB + hB) + inB;    // pre-activation of rowB (g or o)
                float b0 = __shfl_xor_sync(0xffffffffu, a0, 1);
                float b1 = __shfl_xor_sync(0xffffffffu, a1, 1);
                float ipre = od ? b0 : a0;     // SELs, no divergence
                float gpre = od ? b1 : a1;
                float fpre = od ? a0 : b0;
                float opre = od ? a1 : b1;
                float si = fsig(ipre), sf = fsig(fpre);
                float tg = ftanh_(gpre), so = fsig(opre);
                cst[s] = sf * cst[s] + si * tg;
                float h = so * ftanh_(cst[s]);
                if (!od) hspF[cur ^ 1][s][e] = h;
            }

            // rotate the input-term prefetch
            #pragma unroll
            for (int s = 0; s < SEQS; ++s) accI[s] = accN[s];

            __syncthreads();   // single barrier per step: h published, buffers rotated
            cur ^= 1;
        }

        // ---- trailing phase 4 for t = CHUNK-1 (before preamble overwrites paysh) ----
        {
            float2 hv = *(const float2*)&hspF[cur][w][2 * lane];
            float part = fmaf(hv.x, wo0, hv.y * wo1);
            #pragma unroll
            for (int o = 16; o; o >>= 1)
                part += __shfl_xor_sync(0xffffffffu, part, o);
            float raw = fsig(part + bo);
            float pay = paysh[w][CHUNK - 1];
            lossAcc += (double)(raw * nd * pay);
            // last element of chunk: nd NOT updated (matches cumprod over [:-1])
        }
    }

    if (lane == 0) atomicAdd(out, (float)lossAcc);
}

extern "C" void kernel_launch(void* const* d_in, const int* in_sizes, int n_in,
                              void* d_out, int out_size)
{
    const int*   inds        = (const int*)  d_in[0];
    const float* p           = (const float*)d_in[1];
    const float* ls_probs    = (const float*)d_in[2];
    const float* open_probs  = (const float*)d_in[3];
    const int*   open_slices = (const int*)  d_in[4];
    const float* open_hx     = (const float*)d_in[5];
    const float* W_ih        = (const float*)d_in[6];
    const float* W_hh        = (const float*)d_in[7];
    const float* b_ih        = (const float*)d_in[8];
    const float* b_hh        = (const float*)d_in[9];
    const float* W_out       = (const float*)d_in[10];
    const float* b_out       = (const float*)d_in[11];
    const int*   n_chunks    = (n_in > 12) ? (const int*)d_in[12] : nullptr;

    float* out = (float*)d_out;

    pc_zero_kernel<<<1, 32>>>(out);
    pc_lstm_kernel<<<NBLK, NTHR>>>(inds, p, ls_probs, open_probs, open_slices,
                                   open_hx, W_ih, W_hh, b_ih, b_hh,
                                   W_out, b_out, n_chunks, out);
}